// round 14
// baseline (speedup 1.0000x reference)
#include <cuda_runtime.h>
#include <cuda_fp16.h>
#include <cstdint>

#define BB 2
#define SS 2048
#define DM 1024
#define HH 16
#define DH 64
#define NE ((size_t)BB * HH * SS * DH)   // 4M elements per tensor

// Pre-rounded fp16 scratch (allocation-free rule: __device__ globals)
__device__ __half g_xh[NE], g_xl[NE];            // x hi/lo: [tok][1024]
__device__ __half g_wh[3 * HH * DH * DH];        // Wq/Wk/Wv hi: [p][h][o][i]
__device__ __half g_wl[3 * HH * DH * DH];        // lo
__device__ __half g_qh[NE];                      // Q*0.125: [bh][s][d]
__device__ __half g_kh[NE];                      // K:       [bh][s][d]
__device__ __half g_vth[NE];                     // V^T:     [bh][d][s]
__device__ __half g_oh[NE];                      // attnout: [b][s][h*64+d]
__device__ __half g_woh[(size_t)DM * DM];        // Wo

// ---------------------------------------------------------------------------
// fp16 helpers (mma.sync m16n8k16 + ldmatrix + cp.async — compute_103-safe)
// ---------------------------------------------------------------------------
__device__ __forceinline__ void h_split(float x, float& hi, float& lo) {
    hi = __half2float(__float2half_rn(x));
    lo = x - hi;
}
__device__ __forceinline__ uint32_t f22h2(float a, float b) {
    __half2 h = __floats2half2_rn(a, b);
    return *(uint32_t*)&h;
}
__device__ __forceinline__ uint32_t sptr(const void* p) {
    return (uint32_t)__cvta_generic_to_shared(p);
}
__device__ __forceinline__ void ldmx4(uint32_t r[4], uint32_t addr) {
    asm volatile("ldmatrix.sync.aligned.m8n8.x4.shared.b16 {%0,%1,%2,%3}, [%4];"
                 : "=r"(r[0]), "=r"(r[1]), "=r"(r[2]), "=r"(r[3]) : "r"(addr));
}
__device__ __forceinline__ void cpa16(uint32_t dst, const void* src) {
    asm volatile("cp.async.cg.shared.global [%0], [%1], 16;"
                 :: "r"(dst), "l"(src) : "memory");
}
#define CP_COMMIT() asm volatile("cp.async.commit_group;" ::: "memory")
#define CP_WAIT0()  asm volatile("cp.async.wait_group 0;" ::: "memory")
#define CP_WAIT1()  asm volatile("cp.async.wait_group 1;" ::: "memory")
__device__ __forceinline__ void mma_f16(float c[4],
                                        uint32_t a0, uint32_t a1,
                                        uint32_t a2, uint32_t a3,
                                        uint32_t b0, uint32_t b1) {
    asm volatile(
        "mma.sync.aligned.m16n8k16.row.col.f32.f16.f16.f32 "
        "{%0,%1,%2,%3}, {%4,%5,%6,%7}, {%8,%9}, {%0,%1,%2,%3};"
        : "+f"(c[0]), "+f"(c[1]), "+f"(c[2]), "+f"(c[3])
        : "r"(a0), "r"(a1), "r"(a2), "r"(a3), "r"(b0), "r"(b1));
}

#define U32(p) (*(const uint32_t*)&(p))

// ---------------------------------------------------------------------------
// Kernel 0a: one-shot Wo fp16 round (hi only).
// ---------------------------------------------------------------------------
__global__ __launch_bounds__(256) void wsplit_kernel(const float* __restrict__ w)
{
    int i = (blockIdx.x * 256 + threadIdx.x) * 4;
    float4 v = *(const float4*)&w[i];
    *(uint2*)&g_woh[i] = make_uint2(f22h2(v.x, v.y), f22h2(v.z, v.w));
}

// ---------------------------------------------------------------------------
// Kernel 0b: hi/lo split into a global pair at offset (x and Wq/Wk/Wv).
// ---------------------------------------------------------------------------
__global__ __launch_bounds__(256) void gsplit_kernel(
    const float* __restrict__ src, __half* __restrict__ dh,
    __half* __restrict__ dl)
{
    int i = (blockIdx.x * 256 + threadIdx.x) * 4;
    float4 v = *(const float4*)&src[i];
    float h0, l0, h1, l1, h2, l2, h3, l3;
    h_split(v.x, h0, l0); h_split(v.y, h1, l1);
    h_split(v.z, h2, l2); h_split(v.w, h3, l3);
    *(uint2*)&dh[i] = make_uint2(f22h2(h0, h1), f22h2(h2, h3));
    *(uint2*)&dl[i] = make_uint2(f22h2(l0, l1), f22h2(l2, l3));
}

// ---------------------------------------------------------------------------
// Kernel 1: fused QKV projections. All inputs pre-split; staging is pure
// cp.async (x-slice + all 3 weight blocks up front, 2 syncs total).
// ---------------------------------------------------------------------------
#define QST 72   // smem stride in halves (144 B: ldmatrix rows conflict-free)
#define QXB_H (128 * QST)                    // one x region (hi or lo)
#define QWB_H (64 * QST)                     // one W region
#define QKV_SMEM_BYTES ((2 * QXB_H + 6 * QWB_H) * 2)   // 92160

__global__ __launch_bounds__(256, 2) void qkv_mma_kernel(
    const float* __restrict__ bq, const float* __restrict__ bk,
    const float* __restrict__ bv)
{
    extern __shared__ __half qsm[];
    __half* Xh = qsm;
    __half* Xl = qsm + QXB_H;
    const uint32_t sb = sptr(qsm);
    const uint32_t wbase = sb + 2 * QXB_H * 2;

    const int h    = blockIdx.y;
    const int tok0 = blockIdx.x * 128;
    const int tid  = threadIdx.x;
    const int lane = tid & 31, warp = tid >> 5;
    const int gid  = lane >> 2, tig = lane & 3;
    const int wm   = (warp >> 1) * 32;
    const int wn   = (warp & 1) * 32;

    // stage x slice (hi/lo) + all 3 weight blocks (hi/lo) via cp.async
    for (int idx = tid; idx < 1024; idx += 256) {
        int r = idx >> 3, d8 = (idx & 7) << 3;
        uint32_t so = (r * QST + d8) * 2;
        size_t ga = (size_t)(tok0 + r) * DM + h * DH + d8;
        cpa16(sb + so, &g_xh[ga]);
        cpa16(sb + QXB_H * 2 + so, &g_xl[ga]);
    }
    for (int idx = tid; idx < 512 * 3; idx += 256) {
        int p = idx >> 9, j = idx & 511;
        int r = j >> 3, d8 = (j & 7) << 3;
        uint32_t so = (r * QST + d8) * 2;
        size_t ga = (size_t)p * HH * DH * DH + (size_t)h * DH * DH + r * DH + d8;
        cpa16(wbase + p * 2 * QWB_H * 2 + so, &g_wh[ga]);
        cpa16(wbase + (p * 2 + 1) * QWB_H * 2 + so, &g_wl[ga]);
    }
    CP_COMMIT();
    CP_WAIT0();
    __syncthreads();

    const float* bp[3] = {bq, bk, bv};

    for (int p = 0; p < 3; p++) {
        __half* Wh = qsm + 2 * QXB_H + (p * 2) * QWB_H;
        __half* Wl = Wh + QWB_H;

        float c[2][4][4] = {};
#pragma unroll
        for (int ks = 0; ks < 4; ks++) {
            const int kc = ks * 16 + 2 * tig;
            uint32_t ah[2][4], al[2][4];
#pragma unroll
            for (int mt = 0; mt < 2; mt++) {
                int mr = wm + mt * 16 + gid;
                ah[mt][0] = U32(Xh[mr * QST + kc]);
                ah[mt][1] = U32(Xh[(mr + 8) * QST + kc]);
                ah[mt][2] = U32(Xh[mr * QST + kc + 8]);
                ah[mt][3] = U32(Xh[(mr + 8) * QST + kc + 8]);
                al[mt][0] = U32(Xl[mr * QST + kc]);
                al[mt][1] = U32(Xl[(mr + 8) * QST + kc]);
                al[mt][2] = U32(Xl[mr * QST + kc + 8]);
                al[mt][3] = U32(Xl[(mr + 8) * QST + kc + 8]);
            }
#pragma unroll
            for (int nt = 0; nt < 4; nt++) {
                int nr = wn + nt * 8 + gid;
                uint32_t bh0 = U32(Wh[nr * QST + kc]);
                uint32_t bh1 = U32(Wh[nr * QST + kc + 8]);
                uint32_t bl0 = U32(Wl[nr * QST + kc]);
                uint32_t bl1 = U32(Wl[nr * QST + kc + 8]);
#pragma unroll
                for (int mt = 0; mt < 2; mt++) {
                    mma_f16(c[mt][nt], ah[mt][0], ah[mt][1], ah[mt][2], ah[mt][3], bh0, bh1);
                    mma_f16(c[mt][nt], ah[mt][0], ah[mt][1], ah[mt][2], ah[mt][3], bl0, bl1);
                    mma_f16(c[mt][nt], al[mt][0], al[mt][1], al[mt][2], al[mt][3], bh0, bh1);
                }
            }
        }

        // epilogue: +bias, (Q: *0.125), round to fp16, store
#pragma unroll
        for (int mt = 0; mt < 2; mt++) {
#pragma unroll
            for (int nt = 0; nt < 4; nt++) {
                int gtok = tok0 + wm + mt * 16 + gid;
                int o    = wn + nt * 8 + 2 * tig;
                float b0 = bp[p][h * DH + o], b1 = bp[p][h * DH + o + 1];
                int bidx = gtok >> 11;
                int s    = gtok & (SS - 1);
                size_t bh_ = (size_t)bidx * HH + h;
                float r0c0 = c[mt][nt][0] + b0, r0c1 = c[mt][nt][1] + b1;
                float r1c0 = c[mt][nt][2] + b0, r1c1 = c[mt][nt][3] + b1;
                if (p == 0) {
                    r0c0 *= 0.125f; r0c1 *= 0.125f;
                    r1c0 *= 0.125f; r1c1 *= 0.125f;
                }
                if (p < 2) {
                    __half* H = (p == 0) ? g_qh : g_kh;
                    size_t a0 = (bh_ * SS + s) * DH + o;
                    *(uint32_t*)&H[a0] = f22h2(r0c0, r0c1);
                    *(uint32_t*)&H[a0 + 8 * DH] = f22h2(r1c0, r1c1);
                } else {
                    size_t vb0 = (bh_ * DH + o) * SS;
                    size_t vb1 = vb0 + SS;
                    g_vth[vb0 + s]     = __float2half_rn(r0c0);
                    g_vth[vb1 + s]     = __float2half_rn(r0c1);
                    g_vth[vb0 + s + 8] = __float2half_rn(r1c0);
                    g_vth[vb1 + s + 8] = __float2half_rn(r1c1);
                }
            }
        }
    }
}

// ---------------------------------------------------------------------------
// Kernel 2: causal flash attention. Single fp16 operands, P in regs,
// 3-stage cp.async pipeline, ldmatrix fragments.
// ---------------------------------------------------------------------------
#define AQB_H   (128 * QST)                 // Q region, halves
#define KVB_H   (2 * 64 * QST)              // one K/V buffer, halves (Kh,Vh)
#define KVB_B   (KVB_H * 2)                 // 18432 bytes
#define AVH_OFF (64 * QST * 2)              // V offset within buffer
#define ATTN_SMEM_BYTES ((AQB_H + 3 * KVB_H) * 2)   // 73728

__global__ __launch_bounds__(256, 2) void attn_mma_kernel()
{
    extern __shared__ __half asm_[];
    __half* Qh = asm_;
    const uint32_t sb    = sptr(asm_);
    const uint32_t kvb0  = sb + AQB_H * 2;

    const int qt = gridDim.x - 1 - blockIdx.x;   // heavy tiles first
    const int bh = blockIdx.y;
    const int q0 = qt * 128;
    const __half* Qhg = g_qh + (size_t)bh * SS * DH;
    const __half* Khg = g_kh + (size_t)bh * SS * DH;
    const __half* Vhg = g_vth + (size_t)bh * DH * SS;

    const int tid  = threadIdx.x;
    const int warp = tid >> 5, lane = tid & 31;
    const int gid  = lane >> 2, tig = lane & 3;
    const int wr   = warp * 16;

    // ldmatrix lane addressing
    const int arow = (lane & 15), acol = (lane >> 4) << 3;          // A operand
    const int brow = (lane & 7) + ((lane >> 4) << 3);               // B operand
    const int bcol = ((lane >> 3) & 1) << 3;

    const uint32_t qa = sb + ((wr + arow) * QST + acol) * 2;
    uint32_t bofs[4];
#pragma unroll
    for (int np = 0; np < 4; np++)
        bofs[np] = ((np * 16 + brow) * QST + bcol) * 2;

    // stage Q once (pure copy)
    for (int idx = tid; idx < 1024; idx += 256) {
        int r = idx >> 3, d8 = (idx & 7) << 3;
        *(uint4*)&Qh[r * QST + d8] = *(const uint4*)&Qhg[(size_t)(q0 + r) * DH + d8];
    }

    const int nkt = 2 * qt + 2;

    // async stage of K/V tile kt into buffer b
    auto stage_kv = [&](int b, int kt) {
        uint32_t base = kvb0 + b * KVB_B;
        for (int idx = tid; idx < 512; idx += 256) {
            int r = idx >> 3, d8 = (idx & 7) << 3;
            uint32_t so = (r * QST + d8) * 2;
            cpa16(base + so, &Khg[(size_t)(kt * 64 + r) * DH + d8]);
            cpa16(base + AVH_OFF + so, &Vhg[(size_t)r * SS + kt * 64 + d8]);
        }
        CP_COMMIT();
    };

    stage_kv(0, 0);
    stage_kv(1, 1);       // nkt >= 2 always

    float o[8][4] = {};
    float m0 = -1e30f, m1 = -1e30f, l0s = 0.0f, l1s = 0.0f;

    for (int kt = 0; kt < nkt; kt++) {
        CP_WAIT1();                            // tile kt complete
        __syncthreads();                       // visible; prior compute on reuse buffer done
        if (kt + 2 < nkt) {
            stage_kv((kt + 2) % 3, kt + 2);    // overlap with compute of kt
        } else {
            CP_COMMIT();                       // keep group count in sync for CP_WAIT1
        }

        const uint32_t kb = kvb0 + (kt % 3) * KVB_B;

        // S = Q K^T (single fp16 operands)
        float c[8][4] = {};
#pragma unroll
        for (int ks = 0; ks < 4; ks++) {
            uint32_t ah[4];
            ldmx4(ah, qa + ks * 32);
#pragma unroll
            for (int np = 0; np < 4; np++) {
                uint32_t bh4[4];
                ldmx4(bh4, kb + bofs[np] + ks * 32);
                mma_f16(c[2 * np],     ah[0], ah[1], ah[2], ah[3], bh4[0], bh4[1]);
                mma_f16(c[2 * np + 1], ah[0], ah[1], ah[2], ah[3], bh4[2], bh4[3]);
            }
        }

        // causal mask (diagonal band only)
        const int row0 = q0 + wr + gid, row1 = row0 + 8;
        if (kt >= 2 * qt) {
#pragma unroll
            for (int nt = 0; nt < 8; nt++) {
                int col = kt * 64 + nt * 8 + 2 * tig;
                if (col > row0)     c[nt][0] = -1e30f;
                if (col + 1 > row0) c[nt][1] = -1e30f;
                if (col > row1)     c[nt][2] = -1e30f;
                if (col + 1 > row1) c[nt][3] = -1e30f;
            }
        }

        // online softmax (registers, quad shuffle)
        float mx0 = -1e30f, mx1 = -1e30f;
#pragma unroll
        for (int nt = 0; nt < 8; nt++) {
            mx0 = fmaxf(mx0, fmaxf(c[nt][0], c[nt][1]));
            mx1 = fmaxf(mx1, fmaxf(c[nt][2], c[nt][3]));
        }
        mx0 = fmaxf(mx0, __shfl_xor_sync(0xffffffffu, mx0, 1));
        mx0 = fmaxf(mx0, __shfl_xor_sync(0xffffffffu, mx0, 2));
        mx1 = fmaxf(mx1, __shfl_xor_sync(0xffffffffu, mx1, 1));
        mx1 = fmaxf(mx1, __shfl_xor_sync(0xffffffffu, mx1, 2));
        float mn0 = fmaxf(m0, mx0), mn1 = fmaxf(m1, mx1);
        float a0 = __expf(m0 - mn0), a1 = __expf(m1 - mn1);
        m0 = mn0; m1 = mn1;

        // exp + pack P directly into PV A-fragments
        uint32_t pa[4][4];
        float s0 = 0.0f, s1 = 0.0f;
#pragma unroll
        for (int nt = 0; nt < 8; nt++) {
            __half2 p0 = __floats2half2_rn(__expf(c[nt][0] - mn0),
                                           __expf(c[nt][1] - mn0));
            __half2 p1 = __floats2half2_rn(__expf(c[nt][2] - mn1),
                                           __expf(c[nt][3] - mn1));
            float2 pf0 = __half22float2(p0), pf1 = __half22float2(p1);
            s0 += pf0.x + pf0.y;
            s1 += pf1.x + pf1.y;
            int ks = nt >> 1;
            if ((nt & 1) == 0) { pa[ks][0] = U32(p0); pa[ks][1] = U32(p1); }
            else               { pa[ks][2] = U32(p0); pa[ks][3] = U32(p1); }
        }
        s0 += __shfl_xor_sync(0xffffffffu, s0, 1);
        s0 += __shfl_xor_sync(0xffffffffu, s0, 2);
        s1 += __shfl_xor_sync(0xffffffffu, s1, 1);
        s1 += __shfl_xor_sync(0xffffffffu, s1, 2);
        l0s = l0s * a0 + s0;
        l1s = l1s * a1 + s1;

#pragma unroll
        for (int nt = 0; nt < 8; nt++) {
            o[nt][0] *= a0; o[nt][1] *= a0;
            o[nt][2] *= a1; o[nt][3] *= a1;
        }

        // O += P V (single fp16 V)
#pragma unroll
        for (int ks = 0; ks < 4; ks++) {
#pragma unroll
            for (int np = 0; np < 4; np++) {
                uint32_t bh4[4];
                ldmx4(bh4, kb + AVH_OFF + bofs[np] + ks * 32);
                mma_f16(o[2 * np],     pa[ks][0], pa[ks][1], pa[ks][2], pa[ks][3], bh4[0], bh4[1]);
                mma_f16(o[2 * np + 1], pa[ks][0], pa[ks][1], pa[ks][2], pa[ks][3], bh4[2], bh4[3]);
            }
        }
    }

    // epilogue: normalize, write single-fp16 O [b][s][h*64+d]
    const int bidx = bh / HH, h = bh % HH;
    const float i0 = 1.0f / l0s, i1 = 1.0f / l1s;
    const int r0 = q0 + wr + gid;
#pragma unroll
    for (int nt = 0; nt < 8; nt++) {
        int d = nt * 8 + 2 * tig;
        size_t a0 = ((size_t)bidx * SS + r0) * DM + h * DH + d;
        *(uint32_t*)&g_oh[a0] = f22h2(o[nt][0] * i0, o[nt][1] * i0);
        *(uint32_t*)&g_oh[a0 + 8 * DM] = f22h2(o[nt][2] * i1, o[nt][3] * i1);
    }
}

// ---------------------------------------------------------------------------
// Kernel 3: output projection. Single fp16 operands, 3-stage cp.async
// pipeline, ldmatrix fragments.
// ---------------------------------------------------------------------------
#define PAB   (128 * QST * 2)               // one region (A or B), bytes
#define PBUF_B (2 * PAB)                    // 36864 per buffer
#define PROJ_SMEM_BYTES (3 * PBUF_B)        // 110592

__global__ __launch_bounds__(256, 2) void proj_mma_kernel(
    const float* __restrict__ bo, float* __restrict__ out)
{
    extern __shared__ __half psm[];
    const uint32_t sb = sptr(psm);

    const int n0 = blockIdx.x * 128;
    const int m0 = blockIdx.y * 128;
    const int tid  = threadIdx.x;
    const int lane = tid & 31, warp = tid >> 5;
    const int wm = (warp >> 2) * 64;
    const int wn = (warp & 3) * 32;
    const int gid = lane >> 2, tig = lane & 3;

    const int arow = (lane & 15), acol = (lane >> 4) << 3;
    const int brow = (lane & 7) + ((lane >> 4) << 3);
    const int bcol = ((lane >> 3) & 1) << 3;

    uint32_t aofs[4], bofs[2];
#pragma unroll
    for (int mt = 0; mt < 4; mt++)
        aofs[mt] = ((wm + mt * 16 + arow) * QST + acol) * 2;
#pragma unroll
    for (int np = 0; np < 2; np++)
        bofs[np] = ((wn + np * 16 + brow) * QST + bcol) * 2;

    auto stage = [&](int b, int k0) {
        uint32_t base = sb + b * PBUF_B;
        for (int idx = tid; idx < 1024; idx += 256) {
            int r = idx >> 3, q8 = (idx & 7) << 3;
            uint32_t so = (r * QST + q8) * 2;
            cpa16(base + so, &g_oh[(size_t)(m0 + r) * DM + k0 + q8]);
            cpa16(base + PAB + so, &g_woh[(size_t)(n0 + r) * DM + k0 + q8]);
        }
        CP_COMMIT();
    };

    stage(0, 0);
    stage(1, 64);

    float c[4][4][4] = {};

    for (int kc = 0; kc < 16; kc++) {
        CP_WAIT1();
        __syncthreads();
        if (kc + 2 < 16) {
            stage((kc + 2) % 3, (kc + 2) * 64);
        } else {
            CP_COMMIT();
        }

        const uint32_t base = sb + (kc % 3) * PBUF_B;
#pragma unroll
        for (int ks = 0; ks < 4; ks++) {
            uint32_t ah[4][4];
#pragma unroll
            for (int mt = 0; mt < 4; mt++)
                ldmx4(ah[mt], base + aofs[mt] + ks * 32);
#pragma unroll
            for (int np = 0; np < 2; np++) {
                uint32_t bh4[4];
                ldmx4(bh4, base + PAB + bofs[np] + ks * 32);
#pragma unroll
                for (int mt = 0; mt < 4; mt++) {
                    mma_f16(c[mt][2 * np],     ah[mt][0], ah[mt][1], ah[mt][2], ah[mt][3], bh4[0], bh4[1]);
                    mma_f16(c[mt][2 * np + 1], ah[mt][0], ah[mt][1], ah[mt][2], ah[mt][3], bh4[2], bh4[3]);
                }
            }
        }
    }

#pragma unroll
    for (int mt = 0; mt < 4; mt++) {
#pragma unroll
        for (int nt = 0; nt < 4; nt++) {
            int m  = m0 + wm + mt * 16 + gid;
            int n  = n0 + wn + nt * 8 + tig * 2;
            float2 v0, v1;
            v0.x = c[mt][nt][0] + bo[n];
            v0.y = c[mt][nt][1] + bo[n + 1];
            v1.x = c[mt][nt][2] + bo[n];
            v1.y = c[mt][nt][3] + bo[n + 1];
            *(float2*)&out[(size_t)m * DM + n]       = v0;
            *(float2*)&out[(size_t)(m + 8) * DM + n] = v1;
        }
    }
}

// ---------------------------------------------------------------------------
extern "C" void kernel_launch(void* const* d_in, const int* in_sizes, int n_in,
                              void* d_out, int out_size)
{
    const float* x  = (const float*)d_in[0];
    const float* Wq = (const float*)d_in[1];
    const float* bq = (const float*)d_in[2];
    const float* Wk = (const float*)d_in[3];
    const float* bk = (const float*)d_in[4];
    const float* Wv = (const float*)d_in[5];
    const float* bv = (const float*)d_in[6];
    const float* Wo = (const float*)d_in[7];
    const float* bo = (const float*)d_in[8];
    float* out = (float*)d_out;

    cudaFuncSetAttribute(qkv_mma_kernel,
                         cudaFuncAttributeMaxDynamicSharedMemorySize,
                         (int)QKV_SMEM_BYTES);
    cudaFuncSetAttribute(attn_mma_kernel,
                         cudaFuncAttributeMaxDynamicSharedMemorySize,
                         (int)ATTN_SMEM_BYTES);
    cudaFuncSetAttribute(proj_mma_kernel,
                         cudaFuncAttributeMaxDynamicSharedMemorySize,
                         (int)PROJ_SMEM_BYTES);

    __half *p_xh, *p_xl, *p_wh, *p_wl;
    cudaGetSymbolAddress((void**)&p_xh, g_xh);
    cudaGetSymbolAddress((void**)&p_xl, g_xl);
    cudaGetSymbolAddress((void**)&p_wh, g_wh);
    cudaGetSymbolAddress((void**)&p_wl, g_wl);

    const int WSZ = HH * DH * DH;   // 65536 floats per weight tensor
    wsplit_kernel<<<DM * DM / 1024, 256>>>(Wo);
    gsplit_kernel<<<(int)(NE / 1024), 256>>>(x, p_xh, p_xl);
    gsplit_kernel<<<WSZ / 1024, 256>>>(Wq, p_wh, p_wl);
    gsplit_kernel<<<WSZ / 1024, 256>>>(Wk, p_wh + WSZ, p_wl + WSZ);
    gsplit_kernel<<<WSZ / 1024, 256>>>(Wv, p_wh + 2 * WSZ, p_wl + 2 * WSZ);

    qkv_mma_kernel<<<dim3(BB * SS / 128, HH), 256, QKV_SMEM_BYTES>>>(bq, bk, bv);
    attn_mma_kernel<<<dim3(SS / 128, BB * HH), 256, ATTN_SMEM_BYTES>>>();
    proj_mma_kernel<<<dim3(DM / 128, BB * SS / 128), 256, PROJ_SMEM_BYTES>>>(bo, out);
}

// round 15
// speedup vs baseline: 1.0613x; 1.0613x over previous
#include <cuda_runtime.h>
#include <cuda_fp16.h>
#include <cstdint>

#define BB 2
#define SS 2048
#define DM 1024
#define HH 16
#define DH 64
#define NE ((size_t)BB * HH * SS * DH)   // 4M elements per tensor

// Pre-rounded fp16 scratch (allocation-free rule: __device__ globals)
__device__ __half g_xh[NE], g_xl[NE];            // x hi/lo: [tok][1024]
__device__ __half g_wh[3 * HH * DH * DH];        // Wq/Wk/Wv hi: [p][h][o][i]
__device__ __half g_wl[3 * HH * DH * DH];        // lo
__device__ __half g_qh[NE];                      // Q*0.125: [bh][s][d]
__device__ __half g_kh[NE];                      // K:       [bh][s][d]
__device__ __half g_vth[NE];                     // V^T:     [bh][d][s]
__device__ __half g_oh[NE];                      // attnout: [b][s][h*64+d]
__device__ __half g_woh[(size_t)DM * DM];        // Wo

// ---------------------------------------------------------------------------
// fp16 helpers (mma.sync m16n8k16 + ldmatrix + cp.async — compute_103-safe)
// ---------------------------------------------------------------------------
__device__ __forceinline__ void h_split(float x, float& hi, float& lo) {
    hi = __half2float(__float2half_rn(x));
    lo = x - hi;
}
__device__ __forceinline__ uint32_t f22h2(float a, float b) {
    __half2 h = __floats2half2_rn(a, b);
    return *(uint32_t*)&h;
}
__device__ __forceinline__ uint32_t sptr(const void* p) {
    return (uint32_t)__cvta_generic_to_shared(p);
}
__device__ __forceinline__ void ldmx4(uint32_t r[4], uint32_t addr) {
    asm volatile("ldmatrix.sync.aligned.m8n8.x4.shared.b16 {%0,%1,%2,%3}, [%4];"
                 : "=r"(r[0]), "=r"(r[1]), "=r"(r[2]), "=r"(r[3]) : "r"(addr));
}
__device__ __forceinline__ void cpa16(uint32_t dst, const void* src) {
    asm volatile("cp.async.cg.shared.global [%0], [%1], 16;"
                 :: "r"(dst), "l"(src) : "memory");
}
#define CP_COMMIT() asm volatile("cp.async.commit_group;" ::: "memory")
#define CP_WAIT0()  asm volatile("cp.async.wait_group 0;" ::: "memory")
__device__ __forceinline__ void mma_f16(float c[4],
                                        uint32_t a0, uint32_t a1,
                                        uint32_t a2, uint32_t a3,
                                        uint32_t b0, uint32_t b1) {
    asm volatile(
        "mma.sync.aligned.m16n8k16.row.col.f32.f16.f16.f32 "
        "{%0,%1,%2,%3}, {%4,%5,%6,%7}, {%8,%9}, {%0,%1,%2,%3};"
        : "+f"(c[0]), "+f"(c[1]), "+f"(c[2]), "+f"(c[3])
        : "r"(a0), "r"(a1), "r"(a2), "r"(a3), "r"(b0), "r"(b1));
}

#define U32(p) (*(const uint32_t*)&(p))

// ---------------------------------------------------------------------------
// Kernel 0: ONE-LAUNCH prep. blockIdx ranges:
//   [0, 4096)        : x hi/lo split        (4M elems)
//   [4096, 5120)     : Wo fp16 round        (1M elems)
//   [5120, 5312)     : Wq/Wk/Wv hi/lo split (3 x 64K elems)
// ---------------------------------------------------------------------------
__global__ __launch_bounds__(256) void prep_kernel(
    const float* __restrict__ x,  const float* __restrict__ wo,
    const float* __restrict__ wq, const float* __restrict__ wk,
    const float* __restrict__ wv)
{
    const int b = blockIdx.x;
    if (b < 4096) {
        int i = (b * 256 + threadIdx.x) * 4;
        float4 v = *(const float4*)&x[i];
        float h0, l0, h1, l1, h2, l2, h3, l3;
        h_split(v.x, h0, l0); h_split(v.y, h1, l1);
        h_split(v.z, h2, l2); h_split(v.w, h3, l3);
        *(uint2*)&g_xh[i] = make_uint2(f22h2(h0, h1), f22h2(h2, h3));
        *(uint2*)&g_xl[i] = make_uint2(f22h2(l0, l1), f22h2(l2, l3));
    } else if (b < 5120) {
        int i = ((b - 4096) * 256 + threadIdx.x) * 4;
        float4 v = *(const float4*)&wo[i];
        *(uint2*)&g_woh[i] = make_uint2(f22h2(v.x, v.y), f22h2(v.z, v.w));
    } else {
        int j = b - 5120;                 // 0..191, 64 blocks per weight
        int p = j >> 6;
        const float* w = (p == 0) ? wq : (p == 1) ? wk : wv;
        int i = ((j & 63) * 256 + threadIdx.x) * 4;
        float4 v = *(const float4*)&w[i];
        float h0, l0, h1, l1, h2, l2, h3, l3;
        h_split(v.x, h0, l0); h_split(v.y, h1, l1);
        h_split(v.z, h2, l2); h_split(v.w, h3, l3);
        int o = p * (HH * DH * DH) + i;
        *(uint2*)&g_wh[o] = make_uint2(f22h2(h0, h1), f22h2(h2, h3));
        *(uint2*)&g_wl[o] = make_uint2(f22h2(l0, l1), f22h2(l2, l3));
    }
}

// ---------------------------------------------------------------------------
// Kernel 1: fused QKV projections. All inputs pre-split; staging is pure
// cp.async (x-slice + all 3 weight blocks up front, 2 syncs total).
// ---------------------------------------------------------------------------
#define QST 72   // smem stride in halves (144 B: ldmatrix rows conflict-free)
#define QXB_H (128 * QST)                    // one x region (hi or lo)
#define QWB_H (64 * QST)                     // one W region
#define QKV_SMEM_BYTES ((2 * QXB_H + 6 * QWB_H) * 2)   // 92160

__global__ __launch_bounds__(256, 2) void qkv_mma_kernel(
    const float* __restrict__ bq, const float* __restrict__ bk,
    const float* __restrict__ bv)
{
    extern __shared__ __half qsm[];
    __half* Xh = qsm;
    __half* Xl = qsm + QXB_H;
    const uint32_t sb = sptr(qsm);
    const uint32_t wbase = sb + 2 * QXB_H * 2;

    const int h    = blockIdx.y;
    const int tok0 = blockIdx.x * 128;
    const int tid  = threadIdx.x;
    const int lane = tid & 31, warp = tid >> 5;
    const int gid  = lane >> 2, tig = lane & 3;
    const int wm   = (warp >> 1) * 32;
    const int wn   = (warp & 1) * 32;

    // stage x slice (hi/lo) + all 3 weight blocks (hi/lo) via cp.async
    for (int idx = tid; idx < 1024; idx += 256) {
        int r = idx >> 3, d8 = (idx & 7) << 3;
        uint32_t so = (r * QST + d8) * 2;
        size_t ga = (size_t)(tok0 + r) * DM + h * DH + d8;
        cpa16(sb + so, &g_xh[ga]);
        cpa16(sb + QXB_H * 2 + so, &g_xl[ga]);
    }
    for (int idx = tid; idx < 512 * 3; idx += 256) {
        int p = idx >> 9, j = idx & 511;
        int r = j >> 3, d8 = (j & 7) << 3;
        uint32_t so = (r * QST + d8) * 2;
        size_t ga = (size_t)p * HH * DH * DH + (size_t)h * DH * DH + r * DH + d8;
        cpa16(wbase + p * 2 * QWB_H * 2 + so, &g_wh[ga]);
        cpa16(wbase + (p * 2 + 1) * QWB_H * 2 + so, &g_wl[ga]);
    }
    CP_COMMIT();
    CP_WAIT0();
    __syncthreads();

    const float* bp[3] = {bq, bk, bv};

    for (int p = 0; p < 3; p++) {
        __half* Wh = qsm + 2 * QXB_H + (p * 2) * QWB_H;
        __half* Wl = Wh + QWB_H;

        float c[2][4][4] = {};
#pragma unroll
        for (int ks = 0; ks < 4; ks++) {
            const int kc = ks * 16 + 2 * tig;
            uint32_t ah[2][4], al[2][4];
#pragma unroll
            for (int mt = 0; mt < 2; mt++) {
                int mr = wm + mt * 16 + gid;
                ah[mt][0] = U32(Xh[mr * QST + kc]);
                ah[mt][1] = U32(Xh[(mr + 8) * QST + kc]);
                ah[mt][2] = U32(Xh[mr * QST + kc + 8]);
                ah[mt][3] = U32(Xh[(mr + 8) * QST + kc + 8]);
                al[mt][0] = U32(Xl[mr * QST + kc]);
                al[mt][1] = U32(Xl[(mr + 8) * QST + kc]);
                al[mt][2] = U32(Xl[mr * QST + kc + 8]);
                al[mt][3] = U32(Xl[(mr + 8) * QST + kc + 8]);
            }
#pragma unroll
            for (int nt = 0; nt < 4; nt++) {
                int nr = wn + nt * 8 + gid;
                uint32_t bh0 = U32(Wh[nr * QST + kc]);
                uint32_t bh1 = U32(Wh[nr * QST + kc + 8]);
                uint32_t bl0 = U32(Wl[nr * QST + kc]);
                uint32_t bl1 = U32(Wl[nr * QST + kc + 8]);
#pragma unroll
                for (int mt = 0; mt < 2; mt++) {
                    mma_f16(c[mt][nt], ah[mt][0], ah[mt][1], ah[mt][2], ah[mt][3], bh0, bh1);
                    mma_f16(c[mt][nt], ah[mt][0], ah[mt][1], ah[mt][2], ah[mt][3], bl0, bl1);
                    mma_f16(c[mt][nt], al[mt][0], al[mt][1], al[mt][2], al[mt][3], bh0, bh1);
                }
            }
        }

        // epilogue: +bias, (Q: *0.125), round to fp16, store
#pragma unroll
        for (int mt = 0; mt < 2; mt++) {
#pragma unroll
            for (int nt = 0; nt < 4; nt++) {
                int gtok = tok0 + wm + mt * 16 + gid;
                int o    = wn + nt * 8 + 2 * tig;
                float b0 = bp[p][h * DH + o], b1 = bp[p][h * DH + o + 1];
                int bidx = gtok >> 11;
                int s    = gtok & (SS - 1);
                size_t bh_ = (size_t)bidx * HH + h;
                float r0c0 = c[mt][nt][0] + b0, r0c1 = c[mt][nt][1] + b1;
                float r1c0 = c[mt][nt][2] + b0, r1c1 = c[mt][nt][3] + b1;
                if (p == 0) {
                    r0c0 *= 0.125f; r0c1 *= 0.125f;
                    r1c0 *= 0.125f; r1c1 *= 0.125f;
                }
                if (p < 2) {
                    __half* H = (p == 0) ? g_qh : g_kh;
                    size_t a0 = (bh_ * SS + s) * DH + o;
                    *(uint32_t*)&H[a0] = f22h2(r0c0, r0c1);
                    *(uint32_t*)&H[a0 + 8 * DH] = f22h2(r1c0, r1c1);
                } else {
                    size_t vb0 = (bh_ * DH + o) * SS;
                    size_t vb1 = vb0 + SS;
                    g_vth[vb0 + s]     = __float2half_rn(r0c0);
                    g_vth[vb1 + s]     = __float2half_rn(r0c1);
                    g_vth[vb0 + s + 8] = __float2half_rn(r1c0);
                    g_vth[vb1 + s + 8] = __float2half_rn(r1c1);
                }
            }
        }
    }
}

// ---------------------------------------------------------------------------
// Kernel 2: causal flash attention. Single fp16 operands, P in regs,
// 2-stage cp.async double buffer (known good), ldmatrix fragments.
// ---------------------------------------------------------------------------
#define AQB_H   (128 * QST)                 // Q region, halves
#define KVB_H   (2 * 64 * QST)              // one K/V buffer, halves (Kh,Vh)
#define KVB_B   (KVB_H * 2)                 // 18432 bytes
#define AVH_OFF (64 * QST * 2)              // V offset within buffer
#define ATTN_SMEM_BYTES ((AQB_H + 2 * KVB_H) * 2)   // 55296

__global__ __launch_bounds__(256, 2) void attn_mma_kernel()
{
    extern __shared__ __half asm_[];
    __half* Qh = asm_;
    const uint32_t sb    = sptr(asm_);
    const uint32_t kvb0  = sb + AQB_H * 2;

    const int qt = gridDim.x - 1 - blockIdx.x;   // heavy tiles first
    const int bh = blockIdx.y;
    const int q0 = qt * 128;
    const __half* Qhg = g_qh + (size_t)bh * SS * DH;
    const __half* Khg = g_kh + (size_t)bh * SS * DH;
    const __half* Vhg = g_vth + (size_t)bh * DH * SS;

    const int tid  = threadIdx.x;
    const int warp = tid >> 5, lane = tid & 31;
    const int gid  = lane >> 2, tig = lane & 3;
    const int wr   = warp * 16;

    // ldmatrix lane addressing
    const int arow = (lane & 15), acol = (lane >> 4) << 3;          // A operand
    const int brow = (lane & 7) + ((lane >> 4) << 3);               // B operand
    const int bcol = ((lane >> 3) & 1) << 3;

    const uint32_t qa = sb + ((wr + arow) * QST + acol) * 2;
    uint32_t bofs[4];
#pragma unroll
    for (int np = 0; np < 4; np++)
        bofs[np] = ((np * 16 + brow) * QST + bcol) * 2;

    // stage Q once (pure copy)
    for (int idx = tid; idx < 1024; idx += 256) {
        int r = idx >> 3, d8 = (idx & 7) << 3;
        *(uint4*)&Qh[r * QST + d8] = *(const uint4*)&Qhg[(size_t)(q0 + r) * DH + d8];
    }

    const int nkt = 2 * qt + 2;

    // async stage of K/V tile kt into buffer b
    auto stage_kv = [&](int b, int kt) {
        uint32_t base = kvb0 + b * KVB_B;
        for (int idx = tid; idx < 512; idx += 256) {
            int r = idx >> 3, d8 = (idx & 7) << 3;
            uint32_t so = (r * QST + d8) * 2;
            cpa16(base + so, &Khg[(size_t)(kt * 64 + r) * DH + d8]);
            cpa16(base + AVH_OFF + so, &Vhg[(size_t)r * SS + kt * 64 + d8]);
        }
        CP_COMMIT();
    };

    stage_kv(0, 0);

    float o[8][4] = {};
    float m0 = -1e30f, m1 = -1e30f, l0s = 0.0f, l1s = 0.0f;

    for (int kt = 0; kt < nkt; kt++) {
        CP_WAIT0();
        __syncthreads();                       // tile kt visible; prior compute done
        if (kt + 1 < nkt) stage_kv((kt + 1) & 1, kt + 1);   // overlap with compute

        const uint32_t kb = kvb0 + (kt & 1) * KVB_B;

        // S = Q K^T (single fp16 operands)
        float c[8][4] = {};
#pragma unroll
        for (int ks = 0; ks < 4; ks++) {
            uint32_t ah[4];
            ldmx4(ah, qa + ks * 32);
#pragma unroll
            for (int np = 0; np < 4; np++) {
                uint32_t bh4[4];
                ldmx4(bh4, kb + bofs[np] + ks * 32);
                mma_f16(c[2 * np],     ah[0], ah[1], ah[2], ah[3], bh4[0], bh4[1]);
                mma_f16(c[2 * np + 1], ah[0], ah[1], ah[2], ah[3], bh4[2], bh4[3]);
            }
        }

        // causal mask (diagonal band only)
        const int row0 = q0 + wr + gid, row1 = row0 + 8;
        if (kt >= 2 * qt) {
#pragma unroll
            for (int nt = 0; nt < 8; nt++) {
                int col = kt * 64 + nt * 8 + 2 * tig;
                if (col > row0)     c[nt][0] = -1e30f;
                if (col + 1 > row0) c[nt][1] = -1e30f;
                if (col > row1)     c[nt][2] = -1e30f;
                if (col + 1 > row1) c[nt][3] = -1e30f;
            }
        }

        // online softmax (registers, quad shuffle)
        float mx0 = -1e30f, mx1 = -1e30f;
#pragma unroll
        for (int nt = 0; nt < 8; nt++) {
            mx0 = fmaxf(mx0, fmaxf(c[nt][0], c[nt][1]));
            mx1 = fmaxf(mx1, fmaxf(c[nt][2], c[nt][3]));
        }
        mx0 = fmaxf(mx0, __shfl_xor_sync(0xffffffffu, mx0, 1));
        mx0 = fmaxf(mx0, __shfl_xor_sync(0xffffffffu, mx0, 2));
        mx1 = fmaxf(mx1, __shfl_xor_sync(0xffffffffu, mx1, 1));
        mx1 = fmaxf(mx1, __shfl_xor_sync(0xffffffffu, mx1, 2));
        float mn0 = fmaxf(m0, mx0), mn1 = fmaxf(m1, mx1);
        float a0 = __expf(m0 - mn0), a1 = __expf(m1 - mn1);
        m0 = mn0; m1 = mn1;

        // exp + pack P directly into PV A-fragments
        uint32_t pa[4][4];
        float s0 = 0.0f, s1 = 0.0f;
#pragma unroll
        for (int nt = 0; nt < 8; nt++) {
            __half2 p0 = __floats2half2_rn(__expf(c[nt][0] - mn0),
                                           __expf(c[nt][1] - mn0));
            __half2 p1 = __floats2half2_rn(__expf(c[nt][2] - mn1),
                                           __expf(c[nt][3] - mn1));
            float2 pf0 = __half22float2(p0), pf1 = __half22float2(p1);
            s0 += pf0.x + pf0.y;
            s1 += pf1.x + pf1.y;
            int ks = nt >> 1;
            if ((nt & 1) == 0) { pa[ks][0] = U32(p0); pa[ks][1] = U32(p1); }
            else               { pa[ks][2] = U32(p0); pa[ks][3] = U32(p1); }
        }
        s0 += __shfl_xor_sync(0xffffffffu, s0, 1);
        s0 += __shfl_xor_sync(0xffffffffu, s0, 2);
        s1 += __shfl_xor_sync(0xffffffffu, s1, 1);
        s1 += __shfl_xor_sync(0xffffffffu, s1, 2);
        l0s = l0s * a0 + s0;
        l1s = l1s * a1 + s1;

#pragma unroll
        for (int nt = 0; nt < 8; nt++) {
            o[nt][0] *= a0; o[nt][1] *= a0;
            o[nt][2] *= a1; o[nt][3] *= a1;
        }

        // O += P V (single fp16 V)
#pragma unroll
        for (int ks = 0; ks < 4; ks++) {
#pragma unroll
            for (int np = 0; np < 4; np++) {
                uint32_t bh4[4];
                ldmx4(bh4, kb + AVH_OFF + bofs[np] + ks * 32);
                mma_f16(o[2 * np],     pa[ks][0], pa[ks][1], pa[ks][2], pa[ks][3], bh4[0], bh4[1]);
                mma_f16(o[2 * np + 1], pa[ks][0], pa[ks][1], pa[ks][2], pa[ks][3], bh4[2], bh4[3]);
            }
        }
    }

    // epilogue: normalize, write single-fp16 O [b][s][h*64+d]
    const int bidx = bh / HH, h = bh % HH;
    const float i0 = 1.0f / l0s, i1 = 1.0f / l1s;
    const int r0 = q0 + wr + gid;
#pragma unroll
    for (int nt = 0; nt < 8; nt++) {
        int d = nt * 8 + 2 * tig;
        size_t a0 = ((size_t)bidx * SS + r0) * DM + h * DH + d;
        *(uint32_t*)&g_oh[a0] = f22h2(o[nt][0] * i0, o[nt][1] * i0);
        *(uint32_t*)&g_oh[a0 + 8 * DM] = f22h2(o[nt][2] * i1, o[nt][3] * i1);
    }
}

// ---------------------------------------------------------------------------
// Kernel 3: output projection. Single fp16 operands, 2-stage cp.async
// double buffer (known good), ldmatrix fragments.
// ---------------------------------------------------------------------------
#define PAB   (128 * QST * 2)               // one region (A or B), bytes
#define PBUF_B (2 * PAB)                    // 36864 per buffer
#define PROJ_SMEM_BYTES (2 * PBUF_B)        // 73728

__global__ __launch_bounds__(256, 2) void proj_mma_kernel(
    const float* __restrict__ bo, float* __restrict__ out)
{
    extern __shared__ __half psm[];
    const uint32_t sb = sptr(psm);

    const int n0 = blockIdx.x * 128;
    const int m0 = blockIdx.y * 128;
    const int tid  = threadIdx.x;
    const int lane = tid & 31, warp = tid >> 5;
    const int wm = (warp >> 2) * 64;
    const int wn = (warp & 3) * 32;
    const int gid = lane >> 2, tig = lane & 3;

    const int arow = (lane & 15), acol = (lane >> 4) << 3;
    const int brow = (lane & 7) + ((lane >> 4) << 3);
    const int bcol = ((lane >> 3) & 1) << 3;

    uint32_t aofs[4], bofs[2];
#pragma unroll
    for (int mt = 0; mt < 4; mt++)
        aofs[mt] = ((wm + mt * 16 + arow) * QST + acol) * 2;
#pragma unroll
    for (int np = 0; np < 2; np++)
        bofs[np] = ((wn + np * 16 + brow) * QST + bcol) * 2;

    auto stage = [&](int b, int k0) {
        uint32_t base = sb + b * PBUF_B;
        for (int idx = tid; idx < 1024; idx += 256) {
            int r = idx >> 3, q8 = (idx & 7) << 3;
            uint32_t so = (r * QST + q8) * 2;
            cpa16(base + so, &g_oh[(size_t)(m0 + r) * DM + k0 + q8]);
            cpa16(base + PAB + so, &g_woh[(size_t)(n0 + r) * DM + k0 + q8]);
        }
        CP_COMMIT();
    };

    stage(0, 0);

    float c[4][4][4] = {};

    for (int kc = 0; kc < 16; kc++) {
        CP_WAIT0();
        __syncthreads();
        if (kc + 1 < 16) stage((kc + 1) & 1, (kc + 1) * 64);

        const uint32_t base = sb + (kc & 1) * PBUF_B;
#pragma unroll
        for (int ks = 0; ks < 4; ks++) {
            uint32_t ah[4][4];
#pragma unroll
            for (int mt = 0; mt < 4; mt++)
                ldmx4(ah[mt], base + aofs[mt] + ks * 32);
#pragma unroll
            for (int np = 0; np < 2; np++) {
                uint32_t bh4[4];
                ldmx4(bh4, base + PAB + bofs[np] + ks * 32);
#pragma unroll
                for (int mt = 0; mt < 4; mt++) {
                    mma_f16(c[mt][2 * np],     ah[mt][0], ah[mt][1], ah[mt][2], ah[mt][3], bh4[0], bh4[1]);
                    mma_f16(c[mt][2 * np + 1], ah[mt][0], ah[mt][1], ah[mt][2], ah[mt][3], bh4[2], bh4[3]);
                }
            }
        }
    }

#pragma unroll
    for (int mt = 0; mt < 4; mt++) {
#pragma unroll
        for (int nt = 0; nt < 4; nt++) {
            int m  = m0 + wm + mt * 16 + gid;
            int n  = n0 + wn + nt * 8 + tig * 2;
            float2 v0, v1;
            v0.x = c[mt][nt][0] + bo[n];
            v0.y = c[mt][nt][1] + bo[n + 1];
            v1.x = c[mt][nt][2] + bo[n];
            v1.y = c[mt][nt][3] + bo[n + 1];
            *(float2*)&out[(size_t)m * DM + n]       = v0;
            *(float2*)&out[(size_t)(m + 8) * DM + n] = v1;
        }
    }
}

// ---------------------------------------------------------------------------
extern "C" void kernel_launch(void* const* d_in, const int* in_sizes, int n_in,
                              void* d_out, int out_size)
{
    const float* x  = (const float*)d_in[0];
    const float* Wq = (const float*)d_in[1];
    const float* bq = (const float*)d_in[2];
    const float* Wk = (const float*)d_in[3];
    const float* bk = (const float*)d_in[4];
    const float* Wv = (const float*)d_in[5];
    const float* bv = (const float*)d_in[6];
    const float* Wo = (const float*)d_in[7];
    const float* bo = (const float*)d_in[8];
    float* out = (float*)d_out;

    cudaFuncSetAttribute(qkv_mma_kernel,
                         cudaFuncAttributeMaxDynamicSharedMemorySize,
                         (int)QKV_SMEM_BYTES);
    cudaFuncSetAttribute(attn_mma_kernel,
                         cudaFuncAttributeMaxDynamicSharedMemorySize,
                         (int)ATTN_SMEM_BYTES);
    cudaFuncSetAttribute(proj_mma_kernel,
                         cudaFuncAttributeMaxDynamicSharedMemorySize,
                         (int)PROJ_SMEM_BYTES);

    prep_kernel<<<5312, 256>>>(x, Wo, Wq, Wk, Wv);
    qkv_mma_kernel<<<dim3(BB * SS / 128, HH), 256, QKV_SMEM_BYTES>>>(bq, bk, bv);
    attn_mma_kernel<<<dim3(SS / 128, BB * HH), 256, ATTN_SMEM_BYTES>>>();
    proj_mma_kernel<<<dim3(DM / 128, BB * SS / 128), 256, PROJ_SMEM_BYTES>>>(bo, out);
}

// round 17
// speedup vs baseline: 1.1993x; 1.1300x over previous
#include <cuda_runtime.h>
#include <cuda_fp16.h>
#include <cstdint>

#define BB 2
#define SS 2048
#define DM 1024
#define HH 16
#define DH 64
#define NE ((size_t)BB * HH * SS * DH)   // 4M elements per tensor
#define QSCALE (0.125f * 1.4426950408889634f)   // 1/sqrt(64) * log2(e)

// Pre-rounded fp16 scratch (allocation-free rule: __device__ globals)
__device__ __half g_xh[NE], g_xl[NE];            // x hi/lo: [tok][1024]
__device__ __half g_wh[3 * HH * DH * DH];        // Wq/Wk/Wv hi: [p][h][o][i]
__device__ __half g_wl[3 * HH * DH * DH];        // lo
__device__ __half g_qh[NE];                      // Q*0.125*log2e: [bh][s][d]
__device__ __half g_kh[NE];                      // K:       [bh][s][d]
__device__ __half g_vth[NE];                     // V^T:     [bh][d][s]
__device__ __half g_oh[NE];                      // attnout: [b][s][h*64+d]
__device__ __half g_woh[(size_t)DM * DM];        // Wo

// ---------------------------------------------------------------------------
// fp16 helpers (mma.sync m16n8k16 + ldmatrix + cp.async — compute_103-safe)
// ---------------------------------------------------------------------------
__device__ __forceinline__ void h_split(float x, float& hi, float& lo) {
    hi = __half2float(__float2half_rn(x));
    lo = x - hi;
}
__device__ __forceinline__ uint32_t f22h2(float a, float b) {
    __half2 h = __floats2half2_rn(a, b);
    return *(uint32_t*)&h;
}
__device__ __forceinline__ uint32_t sptr(const void* p) {
    return (uint32_t)__cvta_generic_to_shared(p);
}
__device__ __forceinline__ float ex2(float x) {
    float y;
    asm("ex2.approx.ftz.f32 %0, %1;" : "=f"(y) : "f"(x));
    return y;
}
__device__ __forceinline__ void ldmx4(uint32_t r[4], uint32_t addr) {
    asm volatile("ldmatrix.sync.aligned.m8n8.x4.shared.b16 {%0,%1,%2,%3}, [%4];"
                 : "=r"(r[0]), "=r"(r[1]), "=r"(r[2]), "=r"(r[3]) : "r"(addr));
}
__device__ __forceinline__ void cpa16(uint32_t dst, const void* src) {
    asm volatile("cp.async.cg.shared.global [%0], [%1], 16;"
                 :: "r"(dst), "l"(src) : "memory");
}
#define CP_COMMIT() asm volatile("cp.async.commit_group;" ::: "memory")
#define CP_WAIT0()  asm volatile("cp.async.wait_group 0;" ::: "memory")
__device__ __forceinline__ void mma_f16(float c[4],
                                        uint32_t a0, uint32_t a1,
                                        uint32_t a2, uint32_t a3,
                                        uint32_t b0, uint32_t b1) {
    asm volatile(
        "mma.sync.aligned.m16n8k16.row.col.f32.f16.f16.f32 "
        "{%0,%1,%2,%3}, {%4,%5,%6,%7}, {%8,%9}, {%0,%1,%2,%3};"
        : "+f"(c[0]), "+f"(c[1]), "+f"(c[2]), "+f"(c[3])
        : "r"(a0), "r"(a1), "r"(a2), "r"(a3), "r"(b0), "r"(b1));
}

#define U32(p) (*(const uint32_t*)&(p))

// ---------------------------------------------------------------------------
// Kernel 0: ONE-LAUNCH prep. blockIdx ranges:
//   [0, 4096)        : x hi/lo split        (4M elems)
//   [4096, 5120)     : Wo fp16 round        (1M elems)
//   [5120, 5312)     : Wq/Wk/Wv hi/lo split (3 x 64K elems)
// ---------------------------------------------------------------------------
__global__ __launch_bounds__(256) void prep_kernel(
    const float* __restrict__ x,  const float* __restrict__ wo,
    const float* __restrict__ wq, const float* __restrict__ wk,
    const float* __restrict__ wv)
{
    const int b = blockIdx.x;
    if (b < 4096) {
        int i = (b * 256 + threadIdx.x) * 4;
        float4 v = *(const float4*)&x[i];
        float h0, l0, h1, l1, h2, l2, h3, l3;
        h_split(v.x, h0, l0); h_split(v.y, h1, l1);
        h_split(v.z, h2, l2); h_split(v.w, h3, l3);
        *(uint2*)&g_xh[i] = make_uint2(f22h2(h0, h1), f22h2(h2, h3));
        *(uint2*)&g_xl[i] = make_uint2(f22h2(l0, l1), f22h2(l2, l3));
    } else if (b < 5120) {
        int i = ((b - 4096) * 256 + threadIdx.x) * 4;
        float4 v = *(const float4*)&wo[i];
        *(uint2*)&g_woh[i] = make_uint2(f22h2(v.x, v.y), f22h2(v.z, v.w));
    } else {
        int j = b - 5120;                 // 0..191, 64 blocks per weight
        int p = j >> 6;
        const float* w = (p == 0) ? wq : (p == 1) ? wk : wv;
        int i = ((j & 63) * 256 + threadIdx.x) * 4;
        float4 v = *(const float4*)&w[i];
        float h0, l0, h1, l1, h2, l2, h3, l3;
        h_split(v.x, h0, l0); h_split(v.y, h1, l1);
        h_split(v.z, h2, l2); h_split(v.w, h3, l3);
        int o = p * (HH * DH * DH) + i;
        *(uint2*)&g_wh[o] = make_uint2(f22h2(h0, h1), f22h2(h2, h3));
        *(uint2*)&g_wl[o] = make_uint2(f22h2(l0, l1), f22h2(l2, l3));
    }
}

// ---------------------------------------------------------------------------
// Kernel 1: fused QKV projections. All inputs pre-split; staging is pure
// cp.async (x-slice + all 3 weight blocks up front, 2 syncs total).
// ---------------------------------------------------------------------------
#define QST 72   // smem stride in halves (144 B: ldmatrix rows conflict-free)
#define QXB_H (128 * QST)                    // one x region (hi or lo)
#define QWB_H (64 * QST)                     // one W region
#define QKV_SMEM_BYTES ((2 * QXB_H + 6 * QWB_H) * 2)   // 92160

__global__ __launch_bounds__(256, 2) void qkv_mma_kernel(
    const float* __restrict__ bq, const float* __restrict__ bk,
    const float* __restrict__ bv)
{
    extern __shared__ __half qsm[];
    __half* Xh = qsm;
    __half* Xl = qsm + QXB_H;
    const uint32_t sb = sptr(qsm);
    const uint32_t wbase = sb + 2 * QXB_H * 2;

    const int h    = blockIdx.y;
    const int tok0 = blockIdx.x * 128;
    const int tid  = threadIdx.x;
    const int lane = tid & 31, warp = tid >> 5;
    const int gid  = lane >> 2, tig = lane & 3;
    const int wm   = (warp >> 1) * 32;
    const int wn   = (warp & 1) * 32;

    // stage x slice (hi/lo) + all 3 weight blocks (hi/lo) via cp.async
    for (int idx = tid; idx < 1024; idx += 256) {
        int r = idx >> 3, d8 = (idx & 7) << 3;
        uint32_t so = (r * QST + d8) * 2;
        size_t ga = (size_t)(tok0 + r) * DM + h * DH + d8;
        cpa16(sb + so, &g_xh[ga]);
        cpa16(sb + QXB_H * 2 + so, &g_xl[ga]);
    }
    for (int idx = tid; idx < 512 * 3; idx += 256) {
        int p = idx >> 9, j = idx & 511;
        int r = j >> 3, d8 = (j & 7) << 3;
        uint32_t so = (r * QST + d8) * 2;
        size_t ga = (size_t)p * HH * DH * DH + (size_t)h * DH * DH + r * DH + d8;
        cpa16(wbase + p * 2 * QWB_H * 2 + so, &g_wh[ga]);
        cpa16(wbase + (p * 2 + 1) * QWB_H * 2 + so, &g_wl[ga]);
    }
    CP_COMMIT();
    CP_WAIT0();
    __syncthreads();

    const float* bp[3] = {bq, bk, bv};

    for (int p = 0; p < 3; p++) {
        __half* Wh = qsm + 2 * QXB_H + (p * 2) * QWB_H;
        __half* Wl = Wh + QWB_H;

        float c[2][4][4] = {};
#pragma unroll
        for (int ks = 0; ks < 4; ks++) {
            const int kc = ks * 16 + 2 * tig;
            uint32_t ah[2][4], al[2][4];
#pragma unroll
            for (int mt = 0; mt < 2; mt++) {
                int mr = wm + mt * 16 + gid;
                ah[mt][0] = U32(Xh[mr * QST + kc]);
                ah[mt][1] = U32(Xh[(mr + 8) * QST + kc]);
                ah[mt][2] = U32(Xh[mr * QST + kc + 8]);
                ah[mt][3] = U32(Xh[(mr + 8) * QST + kc + 8]);
                al[mt][0] = U32(Xl[mr * QST + kc]);
                al[mt][1] = U32(Xl[(mr + 8) * QST + kc]);
                al[mt][2] = U32(Xl[mr * QST + kc + 8]);
                al[mt][3] = U32(Xl[(mr + 8) * QST + kc + 8]);
            }
#pragma unroll
            for (int nt = 0; nt < 4; nt++) {
                int nr = wn + nt * 8 + gid;
                uint32_t bh0 = U32(Wh[nr * QST + kc]);
                uint32_t bh1 = U32(Wh[nr * QST + kc + 8]);
                uint32_t bl0 = U32(Wl[nr * QST + kc]);
                uint32_t bl1 = U32(Wl[nr * QST + kc + 8]);
#pragma unroll
                for (int mt = 0; mt < 2; mt++) {
                    mma_f16(c[mt][nt], ah[mt][0], ah[mt][1], ah[mt][2], ah[mt][3], bh0, bh1);
                    mma_f16(c[mt][nt], ah[mt][0], ah[mt][1], ah[mt][2], ah[mt][3], bl0, bl1);
                    mma_f16(c[mt][nt], al[mt][0], al[mt][1], al[mt][2], al[mt][3], bh0, bh1);
                }
            }
        }

        // epilogue: +bias, (Q: *0.125*log2e), round to fp16, store
#pragma unroll
        for (int mt = 0; mt < 2; mt++) {
#pragma unroll
            for (int nt = 0; nt < 4; nt++) {
                int gtok = tok0 + wm + mt * 16 + gid;
                int o    = wn + nt * 8 + 2 * tig;
                float b0 = bp[p][h * DH + o], b1 = bp[p][h * DH + o + 1];
                int bidx = gtok >> 11;
                int s    = gtok & (SS - 1);
                size_t bh_ = (size_t)bidx * HH + h;
                float r0c0 = c[mt][nt][0] + b0, r0c1 = c[mt][nt][1] + b1;
                float r1c0 = c[mt][nt][2] + b0, r1c1 = c[mt][nt][3] + b1;
                if (p == 0) {
                    r0c0 *= QSCALE; r0c1 *= QSCALE;
                    r1c0 *= QSCALE; r1c1 *= QSCALE;
                }
                if (p < 2) {
                    __half* H = (p == 0) ? g_qh : g_kh;
                    size_t a0 = (bh_ * SS + s) * DH + o;
                    *(uint32_t*)&H[a0] = f22h2(r0c0, r0c1);
                    *(uint32_t*)&H[a0 + 8 * DH] = f22h2(r1c0, r1c1);
                } else {
                    size_t vb0 = (bh_ * DH + o) * SS;
                    size_t vb1 = vb0 + SS;
                    g_vth[vb0 + s]     = __float2half_rn(r0c0);
                    g_vth[vb1 + s]     = __float2half_rn(r0c1);
                    g_vth[vb0 + s + 8] = __float2half_rn(r1c0);
                    g_vth[vb1 + s + 8] = __float2half_rn(r1c1);
                }
            }
        }
    }
}

// ---------------------------------------------------------------------------
// Kernel 2: causal flash attention. 128-thread CTAs (4 warps, 64 q-rows),
// occupancy 4 — independent CTA phases overlap MUFU softmax with tensor MMA.
// Scores in log2 domain (Q pre-scaled by log2e), ex2.approx for exp.
// ---------------------------------------------------------------------------
#define AQB_H   (64 * QST)                  // Q region, halves
#define KVB_H   (2 * 64 * QST)              // one K/V buffer, halves (Kh,Vh)
#define KVB_B   (KVB_H * 2)                 // 18432 bytes
#define AVH_OFF (64 * QST * 2)              // V offset within buffer
#define ATTN_SMEM_BYTES ((AQB_H + 2 * KVB_H) * 2)   // 46080

__global__ __launch_bounds__(128, 4) void attn_mma_kernel()
{
    extern __shared__ __half asm_[];
    __half* Qh = asm_;
    const uint32_t sb    = sptr(asm_);
    const uint32_t kvb0  = sb + AQB_H * 2;

    const int qt = gridDim.x - 1 - blockIdx.x;   // heavy tiles first
    const int bh = blockIdx.y;
    const int q0 = qt * 64;
    const __half* Qhg = g_qh + (size_t)bh * SS * DH;
    const __half* Khg = g_kh + (size_t)bh * SS * DH;
    const __half* Vhg = g_vth + (size_t)bh * DH * SS;

    const int tid  = threadIdx.x;
    const int warp = tid >> 5, lane = tid & 31;
    const int gid  = lane >> 2, tig = lane & 3;
    const int wr   = warp * 16;

    // ldmatrix lane addressing
    const int arow = (lane & 15), acol = (lane >> 4) << 3;          // A operand
    const int brow = (lane & 7) + ((lane >> 4) << 3);               // B operand
    const int bcol = ((lane >> 3) & 1) << 3;

    const uint32_t qa = sb + ((wr + arow) * QST + acol) * 2;
    uint32_t bofs[4];
#pragma unroll
    for (int np = 0; np < 4; np++)
        bofs[np] = ((np * 16 + brow) * QST + bcol) * 2;

    // stage Q once (pure copy)
    for (int idx = tid; idx < 512; idx += 128) {
        int r = idx >> 3, d8 = (idx & 7) << 3;
        *(uint4*)&Qh[r * QST + d8] = *(const uint4*)&Qhg[(size_t)(q0 + r) * DH + d8];
    }

    const int nkt = qt + 1;

    // async stage of K/V tile kt into buffer b
    auto stage_kv = [&](int b, int kt) {
        uint32_t base = kvb0 + b * KVB_B;
        for (int idx = tid; idx < 512; idx += 128) {
            int r = idx >> 3, d8 = (idx & 7) << 3;
            uint32_t so = (r * QST + d8) * 2;
            cpa16(base + so, &Khg[(size_t)(kt * 64 + r) * DH + d8]);
            cpa16(base + AVH_OFF + so, &Vhg[(size_t)r * SS + kt * 64 + d8]);
        }
        CP_COMMIT();
    };

    stage_kv(0, 0);

    float o[8][4] = {};
    float m0 = -1e30f, m1 = -1e30f, l0s = 0.0f, l1s = 0.0f;

    for (int kt = 0; kt < nkt; kt++) {
        CP_WAIT0();
        __syncthreads();                       // tile kt visible; prior compute done
        if (kt + 1 < nkt) stage_kv((kt + 1) & 1, kt + 1);   // overlap with compute

        const uint32_t kb = kvb0 + (kt & 1) * KVB_B;

        // S(log2) = Q K^T (single fp16 operands)
        float c[8][4] = {};
#pragma unroll
        for (int ks = 0; ks < 4; ks++) {
            uint32_t ah[4];
            ldmx4(ah, qa + ks * 32);
#pragma unroll
            for (int np = 0; np < 4; np++) {
                uint32_t bh4[4];
                ldmx4(bh4, kb + bofs[np] + ks * 32);
                mma_f16(c[2 * np],     ah[0], ah[1], ah[2], ah[3], bh4[0], bh4[1]);
                mma_f16(c[2 * np + 1], ah[0], ah[1], ah[2], ah[3], bh4[2], bh4[3]);
            }
        }

        // causal mask (diagonal tile only)
        const int row0 = q0 + wr + gid, row1 = row0 + 8;
        if (kt == qt) {
#pragma unroll
            for (int nt = 0; nt < 8; nt++) {
                int col = kt * 64 + nt * 8 + 2 * tig;
                if (col > row0)     c[nt][0] = -1e30f;
                if (col + 1 > row0) c[nt][1] = -1e30f;
                if (col > row1)     c[nt][2] = -1e30f;
                if (col + 1 > row1) c[nt][3] = -1e30f;
            }
        }

        // online softmax in log2 domain (registers, quad shuffle)
        float mx0 = -1e30f, mx1 = -1e30f;
#pragma unroll
        for (int nt = 0; nt < 8; nt++) {
            mx0 = fmaxf(mx0, fmaxf(c[nt][0], c[nt][1]));
            mx1 = fmaxf(mx1, fmaxf(c[nt][2], c[nt][3]));
        }
        mx0 = fmaxf(mx0, __shfl_xor_sync(0xffffffffu, mx0, 1));
        mx0 = fmaxf(mx0, __shfl_xor_sync(0xffffffffu, mx0, 2));
        mx1 = fmaxf(mx1, __shfl_xor_sync(0xffffffffu, mx1, 1));
        mx1 = fmaxf(mx1, __shfl_xor_sync(0xffffffffu, mx1, 2));
        float mn0 = fmaxf(m0, mx0), mn1 = fmaxf(m1, mx1);
        float a0 = ex2(m0 - mn0), a1 = ex2(m1 - mn1);
        m0 = mn0; m1 = mn1;

        // exp2 + pack P directly into PV A-fragments
        uint32_t pa[4][4];
        float s0 = 0.0f, s1 = 0.0f;
#pragma unroll
        for (int nt = 0; nt < 8; nt++) {
            __half2 p0 = __floats2half2_rn(ex2(c[nt][0] - mn0),
                                           ex2(c[nt][1] - mn0));
            __half2 p1 = __floats2half2_rn(ex2(c[nt][2] - mn1),
                                           ex2(c[nt][3] - mn1));
            float2 pf0 = __half22float2(p0), pf1 = __half22float2(p1);
            s0 += pf0.x + pf0.y;
            s1 += pf1.x + pf1.y;
            int ks = nt >> 1;
            if ((nt & 1) == 0) { pa[ks][0] = U32(p0); pa[ks][1] = U32(p1); }
            else               { pa[ks][2] = U32(p0); pa[ks][3] = U32(p1); }
        }
        s0 += __shfl_xor_sync(0xffffffffu, s0, 1);
        s0 += __shfl_xor_sync(0xffffffffu, s0, 2);
        s1 += __shfl_xor_sync(0xffffffffu, s1, 1);
        s1 += __shfl_xor_sync(0xffffffffu, s1, 2);
        l0s = l0s * a0 + s0;
        l1s = l1s * a1 + s1;

#pragma unroll
        for (int nt = 0; nt < 8; nt++) {
            o[nt][0] *= a0; o[nt][1] *= a0;
            o[nt][2] *= a1; o[nt][3] *= a1;
        }

        // O += P V (single fp16 V)
#pragma unroll
        for (int ks = 0; ks < 4; ks++) {
#pragma unroll
            for (int np = 0; np < 4; np++) {
                uint32_t bh4[4];
                ldmx4(bh4, kb + AVH_OFF + bofs[np] + ks * 32);
                mma_f16(o[2 * np],     pa[ks][0], pa[ks][1], pa[ks][2], pa[ks][3], bh4[0], bh4[1]);
                mma_f16(o[2 * np + 1], pa[ks][0], pa[ks][1], pa[ks][2], pa[ks][3], bh4[2], bh4[3]);
            }
        }
    }

    // epilogue: normalize, write single-fp16 O [b][s][h*64+d]
    const int bidx = bh / HH, h = bh % HH;
    const float i0 = 1.0f / l0s, i1 = 1.0f / l1s;
    const int r0 = q0 + wr + gid;
#pragma unroll
    for (int nt = 0; nt < 8; nt++) {
        int d = nt * 8 + 2 * tig;
        size_t a0 = ((size_t)bidx * SS + r0) * DM + h * DH + d;
        *(uint32_t*)&g_oh[a0] = f22h2(o[nt][0] * i0, o[nt][1] * i0);
        *(uint32_t*)&g_oh[a0 + 8 * DM] = f22h2(o[nt][2] * i1, o[nt][3] * i1);
    }
}

// ---------------------------------------------------------------------------
// Kernel 3: output projection. Single fp16 operands, 2-stage cp.async
// double buffer, ldmatrix fragments. (unchanged from R15)
// ---------------------------------------------------------------------------
#define PAB   (128 * QST * 2)               // one region (A or B), bytes
#define PBUF_B (2 * PAB)                    // 36864 per buffer
#define PROJ_SMEM_BYTES (2 * PBUF_B)        // 73728

__global__ __launch_bounds__(256, 2) void proj_mma_kernel(
    const float* __restrict__ bo, float* __restrict__ out)
{
    extern __shared__ __half psm[];
    const uint32_t sb = sptr(psm);

    const int n0 = blockIdx.x * 128;
    const int m0 = blockIdx.y * 128;
    const int tid  = threadIdx.x;
    const int lane = tid & 31, warp = tid >> 5;
    const int wm = (warp >> 2) * 64;
    const int wn = (warp & 3) * 32;
    const int gid = lane >> 2, tig = lane & 3;

    const int arow = (lane & 15), acol = (lane >> 4) << 3;
    const int brow = (lane & 7) + ((lane >> 4) << 3);
    const int bcol = ((lane >> 3) & 1) << 3;

    uint32_t aofs[4], bofs[2];
#pragma unroll
    for (int mt = 0; mt < 4; mt++)
        aofs[mt] = ((wm + mt * 16 + arow) * QST + acol) * 2;
#pragma unroll
    for (int np = 0; np < 2; np++)
        bofs[np] = ((wn + np * 16 + brow) * QST + bcol) * 2;

    auto stage = [&](int b, int k0) {
        uint32_t base = sb + b * PBUF_B;
        for (int idx = tid; idx < 1024; idx += 256) {
            int r = idx >> 3, q8 = (idx & 7) << 3;
            uint32_t so = (r * QST + q8) * 2;
            cpa16(base + so, &g_oh[(size_t)(m0 + r) * DM + k0 + q8]);
            cpa16(base + PAB + so, &g_woh[(size_t)(n0 + r) * DM + k0 + q8]);
        }
        CP_COMMIT();
    };

    stage(0, 0);

    float c[4][4][4] = {};

    for (int kc = 0; kc < 16; kc++) {
        CP_WAIT0();
        __syncthreads();
        if (kc + 1 < 16) stage((kc + 1) & 1, (kc + 1) * 64);

        const uint32_t base = sb + (kc & 1) * PBUF_B;
#pragma unroll
        for (int ks = 0; ks < 4; ks++) {
            uint32_t ah[4][4];
#pragma unroll
            for (int mt = 0; mt < 4; mt++)
                ldmx4(ah[mt], base + aofs[mt] + ks * 32);
#pragma unroll
            for (int np = 0; np < 2; np++) {
                uint32_t bh4[4];
                ldmx4(bh4, base + PAB + bofs[np] + ks * 32);
#pragma unroll
                for (int mt = 0; mt < 4; mt++) {
                    mma_f16(c[mt][2 * np],     ah[mt][0], ah[mt][1], ah[mt][2], ah[mt][3], bh4[0], bh4[1]);
                    mma_f16(c[mt][2 * np + 1], ah[mt][0], ah[mt][1], ah[mt][2], ah[mt][3], bh4[2], bh4[3]);
                }
            }
        }
    }

#pragma unroll
    for (int mt = 0; mt < 4; mt++) {
#pragma unroll
        for (int nt = 0; nt < 4; nt++) {
            int m  = m0 + wm + mt * 16 + gid;
            int n  = n0 + wn + nt * 8 + tig * 2;
            float2 v0, v1;
            v0.x = c[mt][nt][0] + bo[n];
            v0.y = c[mt][nt][1] + bo[n + 1];
            v1.x = c[mt][nt][2] + bo[n];
            v1.y = c[mt][nt][3] + bo[n + 1];
            *(float2*)&out[(size_t)m * DM + n]       = v0;
            *(float2*)&out[(size_t)(m + 8) * DM + n] = v1;
        }
    }
}

// ---------------------------------------------------------------------------
extern "C" void kernel_launch(void* const* d_in, const int* in_sizes, int n_in,
                              void* d_out, int out_size)
{
    const float* x  = (const float*)d_in[0];
    const float* Wq = (const float*)d_in[1];
    const float* bq = (const float*)d_in[2];
    const float* Wk = (const float*)d_in[3];
    const float* bk = (const float*)d_in[4];
    const float* Wv = (const float*)d_in[5];
    const float* bv = (const float*)d_in[6];
    const float* Wo = (const float*)d_in[7];
    const float* bo = (const float*)d_in[8];
    float* out = (float*)d_out;

    cudaFuncSetAttribute(qkv_mma_kernel,
                         cudaFuncAttributeMaxDynamicSharedMemorySize,
                         (int)QKV_SMEM_BYTES);
    cudaFuncSetAttribute(attn_mma_kernel,
                         cudaFuncAttributeMaxDynamicSharedMemorySize,
                         (int)ATTN_SMEM_BYTES);
    cudaFuncSetAttribute(proj_mma_kernel,
                         cudaFuncAttributeMaxDynamicSharedMemorySize,
                         (int)PROJ_SMEM_BYTES);

    prep_kernel<<<5312, 256>>>(x, Wo, Wq, Wk, Wv);
    qkv_mma_kernel<<<dim3(BB * SS / 128, HH), 256, QKV_SMEM_BYTES>>>(bq, bk, bv);
    attn_mma_kernel<<<dim3(SS / 64, BB * HH), 128, ATTN_SMEM_BYTES>>>();
    proj_mma_kernel<<<dim3(DM / 128, BB * SS / 128), 256, PROJ_SMEM_BYTES>>>(bo, out);
}